// round 1
// baseline (speedup 1.0000x reference)
#include <cuda_runtime.h>

#define HID 20
#define G4  80
#define EMB 768
#define S_ENC 32768
#define TDEC 285

// ---------------- scratch (static device globals; no dynamic alloc) --------
__device__ float4 g_xg[(size_t)S_ENC * HID];   // encoder gate inputs, [t][j] = (i,f,g,o)
__device__ float4 g_labgx[TDEC * HID];         // teacher-forced decoder gate inputs
__device__ float  g_hc[2 * HID];               // encoder final h (20) then c (20)
__device__ float  g_hd[TDEC * HID];            // decoder h history
__device__ float  g_msum[G4 * HID];            // Whh_d + Wih_d @ Wfc   (80 x 20)
__device__ float4 g_b2[HID];                   // pred-path bias, [j] = (i,f,g,o)

// ---------------- f32x2 helpers --------------------------------------------
__device__ __forceinline__ unsigned long long pack2(float lo, float hi) {
    unsigned long long r;
    asm("mov.b64 %0, {%1, %2};" : "=l"(r) : "f"(lo), "f"(hi));
    return r;
}
__device__ __forceinline__ void unpack2(unsigned long long v, float& lo, float& hi) {
    asm("mov.b64 {%0, %1}, %2;" : "=f"(lo), "=f"(hi) : "l"(v));
}
__device__ __forceinline__ unsigned long long ffma2(unsigned long long a,
                                                    unsigned long long b,
                                                    unsigned long long c) {
    unsigned long long d;
    asm("fma.rn.f32x2 %0, %1, %2, %3;" : "=l"(d) : "l"(a), "l"(b), "l"(c));
    return d;
}
__device__ __forceinline__ unsigned long long fadd2(unsigned long long a,
                                                    unsigned long long b) {
    unsigned long long d;
    asm("add.rn.f32x2 %0, %1, %2;" : "=l"(d) : "l"(a), "l"(b));
    return d;
}

// ---------------- activations ----------------------------------------------
__device__ __forceinline__ float sigm(float x) {
    return __fdividef(1.0f, 1.0f + __expf(-x));
}
__device__ __forceinline__ float tanh_(float x) {
    return __fdividef(2.0f, 1.0f + __expf(-2.0f * x)) - 1.0f;
}

__device__ __forceinline__ void lstm_update(unsigned long long aif,
                                            unsigned long long ago,
                                            float& h, float& c) {
    float gi, gf, gg, go;
    unpack2(aif, gi, gf);
    unpack2(ago, gg, go);
    float is = sigm(gi);
    float fs = sigm(gf);
    float gt = tanh_(gg);
    float os = sigm(go);
    c = fs * c + is * gt;
    h = os * tanh_(c);
}

// ---------------- K1: input GEMM  out[t][j]=(i,f,g,o) = X[t]@W.T + b1 + b2 --
__global__ void k_ingemm(const float* __restrict__ X, const float* __restrict__ W,
                         const float* __restrict__ b1, const float* __restrict__ b2,
                         int dst_flag, int T) {
    __shared__ float xs[32][65];
    __shared__ float ws[80][65];
    float* outp = dst_flag ? (float*)g_labgx : (float*)g_xg;

    int tid = threadIdx.x;            // 128 threads
    int t0  = blockIdx.x * 32;
    int tp  = tid >> 3;               // 0..15 -> 2 timesteps each
    int gs  = tid & 7;                // 0..7  -> 10 gate rows each
    int ta  = t0 + tp * 2;
    int tb  = ta + 1;

    float acc0[10], acc1[10];
#pragma unroll
    for (int jj = 0; jj < 10; jj++) { acc0[jj] = 0.f; acc1[jj] = 0.f; }

    for (int k0 = 0; k0 < EMB; k0 += 64) {
        for (int e = tid; e < 32 * 64; e += 128) {
            int row = e >> 6, col = e & 63;
            int t = t0 + row;
            xs[row][col] = (t < T) ? X[(size_t)t * EMB + k0 + col] : 0.f;
        }
        for (int e = tid; e < 80 * 64; e += 128) {
            int row = e >> 6, col = e & 63;
            ws[row][col] = W[(size_t)row * EMB + k0 + col];
        }
        __syncthreads();
#pragma unroll 4
        for (int k = 0; k < 64; k++) {
            float xa = xs[tp * 2][k];
            float xb = xs[tp * 2 + 1][k];
#pragma unroll
            for (int jj = 0; jj < 10; jj++) {
                float w = ws[gs * 10 + jj][k];
                acc0[jj] += xa * w;
                acc1[jj] += xb * w;
            }
        }
        __syncthreads();
    }

#pragma unroll
    for (int jj = 0; jj < 10; jj++) {
        int r = gs * 10 + jj;
        float bb = b1[r] + b2[r];
        int q = r / HID, j = r % HID;
        if (ta < T) outp[((size_t)ta * HID + j) * 4 + q] = acc0[jj] + bb;
        if (tb < T) outp[((size_t)tb * HID + j) * 4 + q] = acc1[jj] + bb;
    }
}

// ---------------- K2: encoder scan (1 warp, serial over 32768 steps) -------
__global__ void __launch_bounds__(32, 1) k_enc_scan(const float* __restrict__ Whh) {
    int lane = threadIdx.x;
    int j = (lane < HID) ? lane : (HID - 1);

    unsigned long long wif[HID], wgo[HID];
#pragma unroll
    for (int k = 0; k < HID; k++) {
        wif[k] = pack2(Whh[j * HID + k],           Whh[(HID + j) * HID + k]);
        wgo[k] = pack2(Whh[(2 * HID + j) * HID + k], Whh[(3 * HID + j) * HID + k]);
    }

    float h = 0.f, c = 0.f;
    const float4* __restrict__ xg = g_xg;
    float4 cur = xg[0 * HID + j];
    float4 nxt = xg[1 * HID + j];

    for (int t = 0; t < S_ENC; t++) {
        float4 pf = make_float4(0.f, 0.f, 0.f, 0.f);
        if (t + 2 < S_ENC) pf = xg[(size_t)(t + 2) * HID + j];

        unsigned long long aif0 = pack2(cur.x, cur.y);
        unsigned long long ago0 = pack2(cur.z, cur.w);
        unsigned long long aif1 = pack2(0.f, 0.f);
        unsigned long long ago1 = pack2(0.f, 0.f);
#pragma unroll
        for (int k = 0; k < HID; k += 2) {
            float h0 = __shfl_sync(0xffffffffu, h, k);
            float h1 = __shfl_sync(0xffffffffu, h, k + 1);
            unsigned long long h0p = pack2(h0, h0);
            unsigned long long h1p = pack2(h1, h1);
            aif0 = ffma2(h0p, wif[k], aif0);
            ago0 = ffma2(h0p, wgo[k], ago0);
            aif1 = ffma2(h1p, wif[k + 1], aif1);
            ago1 = ffma2(h1p, wgo[k + 1], ago1);
        }
        unsigned long long aif = fadd2(aif0, aif1);
        unsigned long long ago = fadd2(ago0, ago1);
        lstm_update(aif, ago, h, c);
        cur = nxt;
        nxt = pf;
    }

    if (lane < HID) {
        g_hc[lane] = h;
        g_hc[HID + lane] = c;
    }
}

// ---------------- K3: msum = Whh_d + Wih_d @ Wfc ; b2 = Wih_d@bfc + biases --
__global__ void k_msum(const float* __restrict__ Wih_d, const float* __restrict__ Wfc,
                       const float* __restrict__ bfc, const float* __restrict__ Whh_d,
                       const float* __restrict__ bih_d, const float* __restrict__ bhh_d) {
    int r = blockIdx.x;        // 0..79
    int lane = threadIdx.x;    // 32
    float acc[HID + 1];
#pragma unroll
    for (int cc = 0; cc <= HID; cc++) acc[cc] = 0.f;

    for (int e = lane; e < EMB; e += 32) {
        float w = Wih_d[(size_t)r * EMB + e];
#pragma unroll
        for (int cc = 0; cc < HID; cc++) acc[cc] += w * Wfc[e * HID + cc];
        acc[HID] += w * bfc[e];
    }
#pragma unroll
    for (int cc = 0; cc <= HID; cc++) {
        float v = acc[cc];
        for (int o = 16; o; o >>= 1) v += __shfl_xor_sync(0xffffffffu, v, o);
        if (lane == 0) {
            if (cc < HID) {
                g_msum[r * HID + cc] = v + Whh_d[r * HID + cc];
            } else {
                float b = v + bih_d[r] + bhh_d[r];
                ((float*)g_b2)[(r % HID) * 4 + (r / HID)] = b;
            }
        }
    }
}

// ---------------- K4: decoder scan (1 warp, 284 serial steps) --------------
__global__ void __launch_bounds__(32, 1) k_dec_scan(const float* __restrict__ Whh,
                                                    const int* __restrict__ tfm) {
    __shared__ int s_tf[TDEC];
    int lane = threadIdx.x;
    for (int i = lane; i < TDEC; i += 32) s_tf[i] = tfm[i];
    __syncwarp();

    int j = (lane < HID) ? lane : (HID - 1);

    unsigned long long wif[HID], wgo[HID], mif[HID], mgo[HID];
#pragma unroll
    for (int k = 0; k < HID; k++) {
        wif[k] = pack2(Whh[j * HID + k],             Whh[(HID + j) * HID + k]);
        wgo[k] = pack2(Whh[(2 * HID + j) * HID + k], Whh[(3 * HID + j) * HID + k]);
        mif[k] = pack2(g_msum[j * HID + k],             g_msum[(HID + j) * HID + k]);
        mgo[k] = pack2(g_msum[(2 * HID + j) * HID + k], g_msum[(3 * HID + j) * HID + k]);
    }

    float h = g_hc[j];
    float c = g_hc[HID + j];

    for (int t = 1; t < TDEC; t++) {
        int tf = (t == 1) ? 1 : s_tf[t - 1];
        unsigned long long aif0, ago0;
        unsigned long long aif1 = pack2(0.f, 0.f);
        unsigned long long ago1 = pack2(0.f, 0.f);
        if (tf > 0) {
            float4 gx = g_labgx[(t - 1) * HID + j];
            aif0 = pack2(gx.x, gx.y);
            ago0 = pack2(gx.z, gx.w);
#pragma unroll
            for (int k = 0; k < HID; k += 2) {
                float h0 = __shfl_sync(0xffffffffu, h, k);
                float h1 = __shfl_sync(0xffffffffu, h, k + 1);
                unsigned long long h0p = pack2(h0, h0);
                unsigned long long h1p = pack2(h1, h1);
                aif0 = ffma2(h0p, wif[k], aif0);
                ago0 = ffma2(h0p, wgo[k], ago0);
                aif1 = ffma2(h1p, wif[k + 1], aif1);
                ago1 = ffma2(h1p, wgo[k + 1], ago1);
            }
        } else {
            float4 b = g_b2[j];
            aif0 = pack2(b.x, b.y);
            ago0 = pack2(b.z, b.w);
#pragma unroll
            for (int k = 0; k < HID; k += 2) {
                float h0 = __shfl_sync(0xffffffffu, h, k);
                float h1 = __shfl_sync(0xffffffffu, h, k + 1);
                unsigned long long h0p = pack2(h0, h0);
                unsigned long long h1p = pack2(h1, h1);
                aif0 = ffma2(h0p, mif[k], aif0);
                ago0 = ffma2(h0p, mgo[k], ago0);
                aif1 = ffma2(h1p, mif[k + 1], aif1);
                ago1 = ffma2(h1p, mgo[k + 1], ago1);
            }
        }
        unsigned long long aif = fadd2(aif0, aif1);
        unsigned long long ago = fadd2(ago0, ago1);
        lstm_update(aif, ago, h, c);
        if (lane < HID) g_hd[t * HID + lane] = h;
    }
}

// ---------------- K5: output projection  out[t] = h_t @ Wfc.T + bfc --------
__global__ void k_out(const float* __restrict__ Wfc, const float* __restrict__ bfc,
                      float* __restrict__ out) {
    int idx = blockIdx.x * blockDim.x + threadIdx.x;
    if (idx >= TDEC * EMB) return;
    int t = idx / EMB;
    int e = idx - t * EMB;
    if (t == 0) { out[idx] = 0.f; return; }
    const float* h = g_hd + t * HID;
    float a = bfc[e];
#pragma unroll
    for (int k = 0; k < HID; k++) a += h[k] * Wfc[e * HID + k];
    out[idx] = a;
}

// ---------------- launch ----------------------------------------------------
extern "C" void kernel_launch(void* const* d_in, const int* in_sizes, int n_in,
                              void* d_out, int out_size) {
    const float* x     = (const float*)d_in[0];
    const float* label = (const float*)d_in[1];
    const int*   tfm   = (const int*)d_in[2];
    const float* Wih_e = (const float*)d_in[3];
    const float* Whh_e = (const float*)d_in[4];
    const float* bih_e = (const float*)d_in[5];
    const float* bhh_e = (const float*)d_in[6];
    const float* Wih_d = (const float*)d_in[7];
    const float* Whh_d = (const float*)d_in[8];
    const float* bih_d = (const float*)d_in[9];
    const float* bhh_d = (const float*)d_in[10];
    const float* Wfc   = (const float*)d_in[11];
    const float* bfc   = (const float*)d_in[12];
    float* out = (float*)d_out;

    // encoder gate-input GEMM: 32768 x 768 -> 80  (biases folded)
    k_ingemm<<<S_ENC / 32, 128>>>(x, Wih_e, bih_e, bhh_e, 0, S_ENC);
    // decoder teacher-forced gate inputs from labels [0..283]
    k_ingemm<<<(284 + 31) / 32, 128>>>(label, Wih_d, bih_d, bhh_d, 1, 284);
    // fused pred-feedback matrix + bias
    k_msum<<<G4, 32>>>(Wih_d, Wfc, bfc, Whh_d, bih_d, bhh_d);
    // serial scans
    k_enc_scan<<<1, 32>>>(Whh_e);
    k_dec_scan<<<1, 32>>>(Whh_d, tfm);
    // parallel output projection
    k_out<<<(TDEC * EMB + 255) / 256, 256>>>(Wfc, bfc, out);
}

// round 2
// speedup vs baseline: 1.5640x; 1.5640x over previous
#include <cuda_runtime.h>

#define HID 20
#define G4  80
#define EMB 768
#define S_ENC 32768
#define TDEC 285

// ---------------- scratch (static device globals; no dynamic alloc) --------
__device__ float4 g_xg[(size_t)(S_ENC + 8) * HID]; // encoder gate inputs (+8 pad for prefetch)
__device__ float4 g_labgx[TDEC * HID];             // teacher-forced decoder gate inputs
__device__ float  g_hc[2 * HID];                   // encoder final h (20) then c (20)
__device__ float  g_hd[TDEC * HID];                // decoder h history
__device__ float  g_msum[G4 * HID];                // Whh_d + Wih_d @ Wfc   (80 x 20)
__device__ float4 g_b2[HID];                       // pred-path bias, [j] = (i,f,g,o)

typedef unsigned long long ull;

// ---------------- f32x2 helpers --------------------------------------------
__device__ __forceinline__ ull pack2(float lo, float hi) {
    ull r;
    asm("mov.b64 %0, {%1, %2};" : "=l"(r) : "f"(lo), "f"(hi));
    return r;
}
__device__ __forceinline__ void unpack2(ull v, float& lo, float& hi) {
    asm("mov.b64 {%0, %1}, %2;" : "=f"(lo), "=f"(hi) : "l"(v));
}
__device__ __forceinline__ ull ffma2(ull a, ull b, ull c) {
    ull d;
    asm("fma.rn.f32x2 %0, %1, %2, %3;" : "=l"(d) : "l"(a), "l"(b), "l"(c));
    return d;
}
__device__ __forceinline__ ull fmul2(ull a, ull b) {
    ull d;
    asm("mul.rn.f32x2 %0, %1, %2;" : "=l"(d) : "l"(a), "l"(b));
    return d;
}
__device__ __forceinline__ ull fadd2(ull a, ull b) {
    ull d;
    asm("add.rn.f32x2 %0, %1, %2;" : "=l"(d) : "l"(a), "l"(b));
    return d;
}

// ---------------- fast activations (MUFU.TANH) ------------------------------
__device__ __forceinline__ float tanha(float x) {
    float y;
    asm("tanh.approx.f32 %0, %1;" : "=f"(y) : "f"(x));
    return y;
}
__device__ __forceinline__ float sigma(float x) {
    return fmaf(tanha(0.5f * x), 0.5f, 0.5f);
}

// gate dot: (i,f,g,o)_j += h . Whh_row ; pairs over k
// hp[m] = (h_{2m}, h_{2m+1}) ; w[m] = (W[j,2m], W[j,2m+1])
__device__ __forceinline__ float gate_dot(const ull* hp, const ull* w, float gx) {
    ull c0 = ffma2(hp[0], w[0], pack2(gx, 0.f));
    ull c1 = fmul2(hp[1], w[1]);
    c0 = ffma2(hp[2], w[2], c0);
    c1 = ffma2(hp[3], w[3], c1);
    c0 = ffma2(hp[4], w[4], c0);
    c1 = ffma2(hp[5], w[5], c1);
    c0 = ffma2(hp[6], w[6], c0);
    c1 = ffma2(hp[7], w[7], c1);
    c0 = ffma2(hp[8], w[8], c0);
    c1 = ffma2(hp[9], w[9], c1);
    ull s = fadd2(c0, c1);
    float lo, hi;
    unpack2(s, lo, hi);
    return lo + hi;
}

__device__ __forceinline__ void load_hp(ull* hp, unsigned smem_addr) {
    asm volatile("ld.shared.v2.u64 {%0,%1}, [%2];"      : "=l"(hp[0]), "=l"(hp[1]) : "r"(smem_addr));
    asm volatile("ld.shared.v2.u64 {%0,%1}, [%2+16];"   : "=l"(hp[2]), "=l"(hp[3]) : "r"(smem_addr));
    asm volatile("ld.shared.v2.u64 {%0,%1}, [%2+32];"   : "=l"(hp[4]), "=l"(hp[5]) : "r"(smem_addr));
    asm volatile("ld.shared.v2.u64 {%0,%1}, [%2+48];"   : "=l"(hp[6]), "=l"(hp[7]) : "r"(smem_addr));
    asm volatile("ld.shared.v2.u64 {%0,%1}, [%2+64];"   : "=l"(hp[8]), "=l"(hp[9]) : "r"(smem_addr));
}

// ---------------- K1: input GEMM  out[t][j]=(i,f,g,o) = X[t]@W.T + b1 + b2 --
__global__ void k_ingemm(const float* __restrict__ X, const float* __restrict__ W,
                         const float* __restrict__ b1, const float* __restrict__ b2,
                         int dst_flag, int T) {
    __shared__ float xs[32][65];
    __shared__ float ws[80][65];
    float* outp = dst_flag ? (float*)g_labgx : (float*)g_xg;

    int tid = threadIdx.x;            // 128 threads
    int t0  = blockIdx.x * 32;
    int tp  = tid >> 3;               // 0..15 -> 2 timesteps each
    int gs  = tid & 7;                // 0..7  -> 10 gate rows each
    int ta  = t0 + tp * 2;
    int tb  = ta + 1;

    float acc0[10], acc1[10];
#pragma unroll
    for (int jj = 0; jj < 10; jj++) { acc0[jj] = 0.f; acc1[jj] = 0.f; }

    for (int k0 = 0; k0 < EMB; k0 += 64) {
        for (int e = tid; e < 32 * 64; e += 128) {
            int row = e >> 6, col = e & 63;
            int t = t0 + row;
            xs[row][col] = (t < T) ? X[(size_t)t * EMB + k0 + col] : 0.f;
        }
        for (int e = tid; e < 80 * 64; e += 128) {
            int row = e >> 6, col = e & 63;
            ws[row][col] = W[(size_t)row * EMB + k0 + col];
        }
        __syncthreads();
#pragma unroll 4
        for (int k = 0; k < 64; k++) {
            float xa = xs[tp * 2][k];
            float xb = xs[tp * 2 + 1][k];
#pragma unroll
            for (int jj = 0; jj < 10; jj++) {
                float w = ws[gs * 10 + jj][k];
                acc0[jj] += xa * w;
                acc1[jj] += xb * w;
            }
        }
        __syncthreads();
    }

#pragma unroll
    for (int jj = 0; jj < 10; jj++) {
        int r = gs * 10 + jj;
        float bb = b1[r] + b2[r];
        int q = r / HID, j = r % HID;
        if (ta < T) outp[((size_t)ta * HID + j) * 4 + q] = acc0[jj] + bb;
        if (tb < T) outp[((size_t)tb * HID + j) * 4 + q] = acc1[jj] + bb;
    }
}

// ---------------- K2: encoder scan (1 warp, serial over 32768 steps) -------
__global__ void __launch_bounds__(32, 1) k_enc_scan(const float* __restrict__ Whh) {
    int lane = threadIdx.x;
    int j = (lane < HID) ? lane : (HID - 1);

    // weights paired over (k, k+1): w[q][m] = (Whh[q*HID+j][2m], Whh[q*HID+j][2m+1])
    ull w[4][10];
#pragma unroll
    for (int q = 0; q < 4; q++)
#pragma unroll
        for (int m = 0; m < 10; m++)
            w[q][m] = pack2(Whh[(q * HID + j) * HID + 2 * m],
                            Whh[(q * HID + j) * HID + 2 * m + 1]);

    __shared__ __align__(16) float s_h[32];
    s_h[lane] = 0.f;
    __syncwarp();
    unsigned s_addr;
    {
        unsigned long long gp = __cvta_generic_to_shared(&s_h[0]);
        s_addr = (unsigned)gp;
    }

    ull hp[10];
    load_hp(hp, s_addr);

    float h = 0.f, c = 0.f;
    const float4* __restrict__ xg = g_xg;

    float4 buf[8];
#pragma unroll
    for (int u = 0; u < 8; u++) buf[u] = __ldg(&xg[(size_t)u * HID + j]);

    for (int t0 = 0; t0 < S_ENC; t0 += 8) {
#pragma unroll
        for (int u = 0; u < 8; u++) {
            float4 gx = buf[u];
            buf[u] = __ldg(&xg[(size_t)(t0 + 8 + u) * HID + j]);  // prefetch (padded)

            float gi = gate_dot(hp, w[0], gx.x);
            float gf = gate_dot(hp, w[1], gx.y);
            float gg = gate_dot(hp, w[2], gx.z);
            float go = gate_dot(hp, w[3], gx.w);

            c = sigma(gf) * c + sigma(gi) * tanha(gg);
            h = sigma(go) * tanha(c);

            s_h[lane] = h;          // lanes 20..31 write unused slots (no divergence)
            __syncwarp();
            load_hp(hp, s_addr);
        }
    }

    if (lane < HID) {
        g_hc[lane] = h;
        g_hc[HID + lane] = c;
    }
}

// ---------------- K3: msum = Whh_d + Wih_d @ Wfc ; b2 = Wih_d@bfc + biases --
__global__ void k_msum(const float* __restrict__ Wih_d, const float* __restrict__ Wfc,
                       const float* __restrict__ bfc, const float* __restrict__ Whh_d,
                       const float* __restrict__ bih_d, const float* __restrict__ bhh_d) {
    int r = blockIdx.x;        // 0..79
    int lane = threadIdx.x;    // 32
    float acc[HID + 1];
#pragma unroll
    for (int cc = 0; cc <= HID; cc++) acc[cc] = 0.f;

    for (int e = lane; e < EMB; e += 32) {
        float w = Wih_d[(size_t)r * EMB + e];
#pragma unroll
        for (int cc = 0; cc < HID; cc++) acc[cc] += w * Wfc[e * HID + cc];
        acc[HID] += w * bfc[e];
    }
#pragma unroll
    for (int cc = 0; cc <= HID; cc++) {
        float v = acc[cc];
        for (int o = 16; o; o >>= 1) v += __shfl_xor_sync(0xffffffffu, v, o);
        if (lane == 0) {
            if (cc < HID) {
                g_msum[r * HID + cc] = v + Whh_d[r * HID + cc];
            } else {
                float b = v + bih_d[r] + bhh_d[r];
                ((float*)g_b2)[(r % HID) * 4 + (r / HID)] = b;
            }
        }
    }
}

// ---------------- K4: decoder scan (1 warp, 284 serial steps) --------------
__global__ void __launch_bounds__(32, 1) k_dec_scan(const float* __restrict__ Whh,
                                                    const int* __restrict__ tfm) {
    __shared__ int s_tf[TDEC];
    int lane = threadIdx.x;
    for (int i = lane; i < TDEC; i += 32) s_tf[i] = tfm[i];

    int j = (lane < HID) ? lane : (HID - 1);

    ull w[4][10], m[4][10];
#pragma unroll
    for (int q = 0; q < 4; q++)
#pragma unroll
        for (int mm = 0; mm < 10; mm++) {
            w[q][mm] = pack2(Whh[(q * HID + j) * HID + 2 * mm],
                             Whh[(q * HID + j) * HID + 2 * mm + 1]);
            m[q][mm] = pack2(g_msum[(q * HID + j) * HID + 2 * mm],
                             g_msum[(q * HID + j) * HID + 2 * mm + 1]);
        }

    __shared__ __align__(16) float s_h[32];
    float h = g_hc[j];
    float c = g_hc[HID + j];
    s_h[lane] = h;
    __syncwarp();
    unsigned s_addr;
    {
        unsigned long long gp = __cvta_generic_to_shared(&s_h[0]);
        s_addr = (unsigned)gp;
    }
    ull hp[10];
    load_hp(hp, s_addr);

    float4 b2 = g_b2[j];

    for (int t = 1; t < TDEC; t++) {
        int tf = (t == 1) ? 1 : s_tf[t - 1];
        float gi, gf, gg, go;
        if (tf > 0) {
            float4 gx = g_labgx[(t - 1) * HID + j];
            gi = gate_dot(hp, w[0], gx.x);
            gf = gate_dot(hp, w[1], gx.y);
            gg = gate_dot(hp, w[2], gx.z);
            go = gate_dot(hp, w[3], gx.w);
        } else {
            gi = gate_dot(hp, m[0], b2.x);
            gf = gate_dot(hp, m[1], b2.y);
            gg = gate_dot(hp, m[2], b2.z);
            go = gate_dot(hp, m[3], b2.w);
        }
        c = sigma(gf) * c + sigma(gi) * tanha(gg);
        h = sigma(go) * tanha(c);

        s_h[lane] = h;
        __syncwarp();
        load_hp(hp, s_addr);

        if (lane < HID) g_hd[t * HID + lane] = h;
    }
}

// ---------------- K5: output projection  out[t] = h_t @ Wfc.T + bfc --------
__global__ void k_out(const float* __restrict__ Wfc, const float* __restrict__ bfc,
                      float* __restrict__ out) {
    int idx = blockIdx.x * blockDim.x + threadIdx.x;
    if (idx >= TDEC * EMB) return;
    int t = idx / EMB;
    int e = idx - t * EMB;
    if (t == 0) { out[idx] = 0.f; return; }
    const float* h = g_hd + t * HID;
    float a = bfc[e];
#pragma unroll
    for (int k = 0; k < HID; k++) a += h[k] * Wfc[e * HID + k];
    out[idx] = a;
}

// ---------------- launch ----------------------------------------------------
extern "C" void kernel_launch(void* const* d_in, const int* in_sizes, int n_in,
                              void* d_out, int out_size) {
    const float* x     = (const float*)d_in[0];
    const float* label = (const float*)d_in[1];
    const int*   tfm   = (const int*)d_in[2];
    const float* Wih_e = (const float*)d_in[3];
    const float* Whh_e = (const float*)d_in[4];
    const float* bih_e = (const float*)d_in[5];
    const float* bhh_e = (const float*)d_in[6];
    const float* Wih_d = (const float*)d_in[7];
    const float* Whh_d = (const float*)d_in[8];
    const float* bih_d = (const float*)d_in[9];
    const float* bhh_d = (const float*)d_in[10];
    const float* Wfc   = (const float*)d_in[11];
    const float* bfc   = (const float*)d_in[12];
    float* out = (float*)d_out;

    // encoder gate-input GEMM: 32768 x 768 -> 80  (biases folded)
    k_ingemm<<<S_ENC / 32, 128>>>(x, Wih_e, bih_e, bhh_e, 0, S_ENC);
    // decoder teacher-forced gate inputs from labels [0..283]
    k_ingemm<<<(284 + 31) / 32, 128>>>(label, Wih_d, bih_d, bhh_d, 1, 284);
    // fused pred-feedback matrix + bias
    k_msum<<<G4, 32>>>(Wih_d, Wfc, bfc, Whh_d, bih_d, bhh_d);
    // serial scans
    k_enc_scan<<<1, 32>>>(Whh_e);
    k_dec_scan<<<1, 32>>>(Whh_d, tfm);
    // parallel output projection
    k_out<<<(TDEC * EMB + 255) / 256, 256>>>(Wfc, bfc, out);
}